// round 5
// baseline (speedup 1.0000x reference)
#include <cuda_runtime.h>
#include <cstdint>

#define EDIM 256

__device__ float g_pref[2048 * EDIM];
__device__ int   g_mask_mode;

static __device__ __forceinline__ float tf32_rna(float x){
    uint32_t r; asm("cvt.rna.tf32.f32 %0, %1;" : "=r"(r) : "f"(x));
    return __uint_as_float(r);
}
static __device__ __forceinline__ uint32_t smem_u32(const void* p){
    uint32_t a;
    asm("{ .reg .u64 t; cvta.to.shared.u64 t, %1; cvt.u32.u64 %0, t; }" : "=r"(a) : "l"(p));
    return a;
}
static __device__ __forceinline__ void cp_async16(uint32_t dst, const void* src, int src_bytes){
    asm volatile("cp.async.ca.shared.global [%0], [%1], 16, %2;"
                 :: "r"(dst), "l"(src), "r"(src_bytes) : "memory");
}
#define CP_COMMIT() asm volatile("cp.async.commit_group;" ::: "memory")
#define CP_WAIT(n)  asm volatile("cp.async.wait_group %0;" :: "n"(n) : "memory")

static __device__ __forceinline__ void mma_tf32(float* d, const float* a, const float* b){
    asm volatile(
        "mma.sync.aligned.m16n8k8.row.col.f32.tf32.tf32.f32 "
        "{%0,%1,%2,%3}, {%4,%5,%6,%7}, {%8,%9}, {%0,%1,%2,%3};"
        : "+f"(d[0]), "+f"(d[1]), "+f"(d[2]), "+f"(d[3])
        : "r"(__float_as_uint(a[0])), "r"(__float_as_uint(a[1])),
          "r"(__float_as_uint(a[2])), "r"(__float_as_uint(a[3])),
          "r"(__float_as_uint(b[0])), "r"(__float_as_uint(b[1])));
}

// ---------------- kernel 0: detect path_mask dtype ----------------
__global__ void detect_mask_kernel(const unsigned int* __restrict__ m){
    __shared__ int sf, sg;
    if (threadIdx.x == 0){ sf = 0; sg = 0; }
    __syncthreads();
    int lf = 0, lg = 0;
    for (int i = threadIdx.x; i < 3072; i += blockDim.x){
        unsigned v = m[i];
        if (v == 0x3F800000u) lf = 1;
        else if (v > 1u) lg = 1;
    }
    if (lf) atomicOr(&sf, 1);
    if (lg) atomicOr(&sg, 1);
    __syncthreads();
    if (threadIdx.x == 0) g_mask_mode = sf ? 2 : (sg ? 1 : 0);
}

// ---------------- kernel 1: attention -> g_pref ----------------
__global__ void __launch_bounds__(128)
attn_kernel(const int* __restrict__ user, const int* __restrict__ last_poi,
            const int* __restrict__ path_nodes, const void* __restrict__ mask,
            const int* __restrict__ nn_ptr,
            const float* __restrict__ poi_emb, const float* __restrict__ tree_emb,
            const float* __restrict__ w1, const float* __restrict__ b1,
            const float* __restrict__ w2, const float* __restrict__ b2)
{
    const int b = blockIdx.x, t = threadIdx.x;
    const int wid = t >> 5, lane = t & 31;
    __shared__ float lp[EDIM];
    __shared__ float pp[6][EDIM];
    __shared__ float hh[6][EDIM];
    __shared__ float red[6][4];

    const int mode = g_mask_mode;
    const int nn = nn_ptr ? nn_ptr[0] : 63;
    const int u = user[b];
    const int poi = last_poi[b];

    int nodes[6]; bool msk[6];
    #pragma unroll
    for (int l = 0; l < 6; l++) nodes[l] = path_nodes[b*6 + l];
    if (mode == 2){
        const float* mm = (const float*)mask;
        #pragma unroll
        for (int l = 0; l < 6; l++) msk[l] = (mm[b*6+l] != 0.f);
    } else if (mode == 1){
        const unsigned char* mm = (const unsigned char*)mask;
        #pragma unroll
        for (int l = 0; l < 6; l++) msk[l] = (mm[b*6+l] != 0);
    } else {
        const int* mm = (const int*)mask;
        #pragma unroll
        for (int l = 0; l < 6; l++) msk[l] = (mm[b*6+l] != 0);
    }

    for (int e = t; e < EDIM; e += 128) lp[e] = poi_emb[(size_t)poi*EDIM + e];
    for (int i = t; i < 6*EDIM; i += 128){
        int l = i >> 8, e = i & 255;
        pp[l][e] = tree_emb[((size_t)u*nn + nodes[l])*EDIM + e];
    }
    __syncthreads();
    for (int i = t; i < 6*EDIM; i += 128){
        int l = i >> 8, e = i & 255;
        hh[l][e] = tanhf(lp[e] + pp[l][e]);
    }
    __syncthreads();

    float acc[6] = {0.f,0.f,0.f,0.f,0.f,0.f};
    for (int e = 0; e < EDIM; e++){
        float w = w1[e*128 + t];
        #pragma unroll
        for (int l = 0; l < 6; l++) acc[l] += hh[l][e] * w;
    }
    const float b1j = b1[t], w2j = w2[t];
    float part[6];
    #pragma unroll
    for (int l = 0; l < 6; l++) part[l] = fmaxf(acc[l] + b1j, 0.f) * w2j;
    #pragma unroll
    for (int o = 16; o > 0; o >>= 1){
        #pragma unroll
        for (int l = 0; l < 6; l++) part[l] += __shfl_xor_sync(0xFFFFFFFFu, part[l], o);
    }
    if (lane == 0){
        #pragma unroll
        for (int l = 0; l < 6; l++) red[l][wid] = part[l];
    }
    __syncthreads();

    const float b2v = b2[0];
    float a[6], amax = -3.0e38f;
    #pragma unroll
    for (int l = 0; l < 6; l++){
        float v = red[l][0] + red[l][1] + red[l][2] + red[l][3] + b2v;
        if (!msk[l]) v = -1e9f;
        a[l] = v; amax = fmaxf(amax, v);
    }
    float s = 0.f, aw[6];
    #pragma unroll
    for (int l = 0; l < 6; l++){ aw[l] = expf(a[l] - amax); s += aw[l]; }
    const float inv = 1.f / s;
    for (int e = t; e < EDIM; e += 128){
        float o = 0.f;
        #pragma unroll
        for (int l = 0; l < 6; l++) o += aw[l] * pp[l][e];
        g_pref[(size_t)b*EDIM + e] = tf32_rna(o * inv);
    }
}

// ---------------- kernel 2: GEMM scores = pref @ poi_emb^T (mma.sync tf32) ----------------
// Tile 128x128, K-chunks of 32, 3-stage cp.async pipeline, 1 sync per chunk.
// Stage: A[128][36] + B[128][36] floats (pad 36 -> conflict-free fragment LDS).
#define ROWF 36
#define HALF_STAGE (128*ROWF*4)             // 18432 bytes (A or B)
#define STAGE_BYTES (2*HALF_STAGE)          // 36864
#define NSTAGE 3
#define GSMEM_BYTES (NSTAGE*STAGE_BYTES)    // 110592

__global__ void __launch_bounds__(256, 1)
gemm_kernel(const float* __restrict__ Bmat, float* __restrict__ out,
            int Brows, int Ncols)
{
    extern __shared__ char smem[];
    const uint32_t sb = smem_u32(smem);
    const int t = threadIdx.x;
    const int wid = t >> 5, lane = t & 31;
    const int g = lane >> 2, tq = lane & 3;
    const int wm = wid & 1, wn = wid >> 1;        // 2 x 4 warp grid
    const int m_base = blockIdx.x * 128;
    const int n_base = blockIdx.y * 128;

    const int lrow = t >> 3;          // 0..31 (32 rows per pass, 4 passes)
    const int lseg = t & 7;           // 16B segment within 128B row

    float acc[4][4][4];
    #pragma unroll
    for (int i = 0; i < 4; i++)
        #pragma unroll
        for (int j = 0; j < 4; j++)
            #pragma unroll
            for (int r = 0; r < 4; r++) acc[i][j][r] = 0.f;

    // prefetch K-chunk kc into stage slot kc % NSTAGE (always commits a group)
    auto prefetch = [&](int kc){
        if (kc < 8){
            const uint32_t base = sb + (kc % NSTAGE)*STAGE_BYTES;
            #pragma unroll
            for (int it = 0; it < 4; it++){
                int row = lrow + it*32;
                cp_async16(base + row*(ROWF*4) + lseg*16,
                           &g_pref[(size_t)(m_base+row)*EDIM + kc*32 + lseg*4], 16);
            }
            #pragma unroll
            for (int it = 0; it < 4; it++){
                int row = lrow + it*32;
                int gn = n_base + row;
                const float* src = &Bmat[(size_t)(gn < Ncols ? gn : 0)*EDIM + kc*32 + lseg*4];
                cp_async16(base + HALF_STAGE + row*(ROWF*4) + lseg*16, src, gn < Ncols ? 16 : 0);
            }
        }
        CP_COMMIT();
    };

    prefetch(0);
    prefetch(1);

    for (int kc = 0; kc < 8; kc++){
        CP_WAIT(NSTAGE - 2);      // chunk kc resident
        __syncthreads();          // also orders slot reuse (readers of kc-1 done)
        prefetch(kc + 2);         // fills slot (kc+2)%3 = (kc-1)%3, safe after sync

        const float* As_ = (const float*)(smem + (kc % NSTAGE)*STAGE_BYTES);
        const float* Bs_ = (const float*)(smem + (kc % NSTAGE)*STAGE_BYTES + HALF_STAGE);

        #pragma unroll
        for (int ks = 0; ks < 4; ks++){
            const int k = ks * 8;
            float a[4][4], bf[4][2];
            #pragma unroll
            for (int i = 0; i < 4; i++){
                int r0 = wm*64 + i*16 + g;
                a[i][0] = As_[r0*ROWF + k + tq];
                a[i][1] = As_[(r0+8)*ROWF + k + tq];
                a[i][2] = As_[r0*ROWF + k + tq + 4];
                a[i][3] = As_[(r0+8)*ROWF + k + tq + 4];
            }
            #pragma unroll
            for (int j = 0; j < 4; j++){
                int n0 = wn*32 + j*8 + g;
                bf[j][0] = tf32_rna(Bs_[n0*ROWF + k + tq]);
                bf[j][1] = tf32_rna(Bs_[n0*ROWF + k + tq + 4]);
            }
            #pragma unroll
            for (int i = 0; i < 4; i++)
                #pragma unroll
                for (int j = 0; j < 4; j++)
                    mma_tf32(acc[i][j], a[i], bf[j]);
        }
    }

    // epilogue: streaming float2 stores
    #pragma unroll
    for (int i = 0; i < 4; i++){
        const int row0 = m_base + wm*64 + i*16 + g;
        #pragma unroll
        for (int j = 0; j < 4; j++){
            const int col = n_base + wn*32 + j*8 + 2*tq;
            if (col < Ncols && row0 < Brows){
                float2 v0 = make_float2(acc[i][j][0], acc[i][j][1]);
                float2 v1 = make_float2(acc[i][j][2], acc[i][j][3]);
                __stcs(reinterpret_cast<float2*>(&out[(size_t)row0*Ncols + col]), v0);
                __stcs(reinterpret_cast<float2*>(&out[(size_t)(row0+8)*Ncols + col]), v1);
            }
        }
    }
}

// ---------------- launch ----------------
extern "C" void kernel_launch(void* const* d_in, const int* in_sizes, int n_in,
                              void* d_out, int out_size)
{
    const int* user       = (const int*)d_in[0];
    const int* last_poi   = (const int*)d_in[1];
    const int* path_nodes = (const int*)d_in[2];
    const void* mask      = d_in[3];
    const int* nn_ptr = nullptr;
    int k = 4;
    if (n_in >= 11){ nn_ptr = (const int*)d_in[4]; k = 5; }
    const float* poi_emb  = (const float*)d_in[k+0];
    const float* tree_emb = (const float*)d_in[k+1];
    const float* w1 = (const float*)d_in[k+2];
    const float* b1 = (const float*)d_in[k+3];
    const float* w2 = (const float*)d_in[k+4];
    const float* b2 = (const float*)d_in[k+5];
    float* out = (float*)d_out;

    const int B  = in_sizes[0];
    const int NP = in_sizes[k+0] / EDIM;
    const int gridM = (B + 127) / 128;
    const int gridN = (NP + 127) / 128;

    detect_mask_kernel<<<1, 256>>>((const unsigned int*)mask);
    attn_kernel<<<B, 128>>>(user, last_poi, path_nodes, mask, nn_ptr,
                            poi_emb, tree_emb, w1, b1, w2, b2);
    cudaFuncSetAttribute(gemm_kernel,
                         cudaFuncAttributeMaxDynamicSharedMemorySize, GSMEM_BYTES);
    dim3 grid(gridM, gridN);
    gemm_kernel<<<grid, 256, GSMEM_BYTES>>>(poi_emb, out, B, NP);
}

// round 6
// speedup vs baseline: 1.4706x; 1.4706x over previous
#include <cuda_runtime.h>
#include <cuda_fp16.h>
#include <cstdint>

#define EDIM 256

__device__ __half g_prefh[2048 * EDIM];
__device__ __half g_bh[100000 * EDIM];
__device__ int    g_mask_mode;

static __device__ __forceinline__ uint32_t smem_u32(const void* p){
    uint32_t a;
    asm("{ .reg .u64 t; cvta.to.shared.u64 t, %1; cvt.u32.u64 %0, t; }" : "=r"(a) : "l"(p));
    return a;
}
static __device__ __forceinline__ void cp_async16(uint32_t dst, const void* src, int src_bytes){
    asm volatile("cp.async.ca.shared.global [%0], [%1], 16, %2;"
                 :: "r"(dst), "l"(src), "r"(src_bytes) : "memory");
}
#define CP_COMMIT() asm volatile("cp.async.commit_group;" ::: "memory")
#define CP_WAIT(n)  asm volatile("cp.async.wait_group %0;" :: "n"(n) : "memory")

static __device__ __forceinline__ void mma_f16(float* d, const uint32_t* a,
                                               uint32_t b0, uint32_t b1){
    asm volatile(
        "mma.sync.aligned.m16n8k16.row.col.f32.f16.f16.f32 "
        "{%0,%1,%2,%3}, {%4,%5,%6,%7}, {%8,%9}, {%0,%1,%2,%3};"
        : "+f"(d[0]), "+f"(d[1]), "+f"(d[2]), "+f"(d[3])
        : "r"(a[0]), "r"(a[1]), "r"(a[2]), "r"(a[3]), "r"(b0), "r"(b1));
}

// ---------------- kernel 0: detect path_mask dtype ----------------
__global__ void detect_mask_kernel(const unsigned int* __restrict__ m){
    __shared__ int sf, sg;
    if (threadIdx.x == 0){ sf = 0; sg = 0; }
    __syncthreads();
    int lf = 0, lg = 0;
    for (int i = threadIdx.x; i < 3072; i += blockDim.x){
        unsigned v = m[i];
        if (v == 0x3F800000u) lf = 1;
        else if (v > 1u) lg = 1;
    }
    if (lf) atomicOr(&sf, 1);
    if (lg) atomicOr(&sg, 1);
    __syncthreads();
    if (threadIdx.x == 0) g_mask_mode = sf ? 2 : (sg ? 1 : 0);
}

// ---------------- kernel 0b: poi_emb fp32 -> fp16 ----------------
__global__ void __launch_bounds__(256)
convert_b_kernel(const float* __restrict__ B, int n){
    int i = (blockIdx.x * 256 + threadIdx.x) * 8;
    if (i + 8 <= n){
        float4 v0 = *reinterpret_cast<const float4*>(B + i);
        float4 v1 = *reinterpret_cast<const float4*>(B + i + 4);
        __half2 h0 = __floats2half2_rn(v0.x, v0.y);
        __half2 h1 = __floats2half2_rn(v0.z, v0.w);
        __half2 h2 = __floats2half2_rn(v1.x, v1.y);
        __half2 h3 = __floats2half2_rn(v1.z, v1.w);
        uint4 o;
        o.x = *reinterpret_cast<uint32_t*>(&h0);
        o.y = *reinterpret_cast<uint32_t*>(&h1);
        o.z = *reinterpret_cast<uint32_t*>(&h2);
        o.w = *reinterpret_cast<uint32_t*>(&h3);
        *reinterpret_cast<uint4*>(&g_bh[i]) = o;
    } else {
        for (int j = i; j < n; j++) g_bh[j] = __float2half_rn(B[j]);
    }
}

// ---------------- kernel 1: attention -> g_prefh ----------------
__global__ void __launch_bounds__(128)
attn_kernel(const int* __restrict__ user, const int* __restrict__ last_poi,
            const int* __restrict__ path_nodes, const void* __restrict__ mask,
            const int* __restrict__ nn_ptr,
            const float* __restrict__ poi_emb, const float* __restrict__ tree_emb,
            const float* __restrict__ w1, const float* __restrict__ b1,
            const float* __restrict__ w2, const float* __restrict__ b2)
{
    const int b = blockIdx.x, t = threadIdx.x;
    const int wid = t >> 5, lane = t & 31;
    __shared__ float lp[EDIM];
    __shared__ float pp[6][EDIM];
    __shared__ float hh[6][EDIM];
    __shared__ float red[6][4];

    const int mode = g_mask_mode;
    const int nn = nn_ptr ? nn_ptr[0] : 63;
    const int u = user[b];
    const int poi = last_poi[b];

    int nodes[6]; bool msk[6];
    #pragma unroll
    for (int l = 0; l < 6; l++) nodes[l] = path_nodes[b*6 + l];
    if (mode == 2){
        const float* mm = (const float*)mask;
        #pragma unroll
        for (int l = 0; l < 6; l++) msk[l] = (mm[b*6+l] != 0.f);
    } else if (mode == 1){
        const unsigned char* mm = (const unsigned char*)mask;
        #pragma unroll
        for (int l = 0; l < 6; l++) msk[l] = (mm[b*6+l] != 0);
    } else {
        const int* mm = (const int*)mask;
        #pragma unroll
        for (int l = 0; l < 6; l++) msk[l] = (mm[b*6+l] != 0);
    }

    for (int e = t; e < EDIM; e += 128) lp[e] = poi_emb[(size_t)poi*EDIM + e];
    for (int i = t; i < 6*EDIM; i += 128){
        int l = i >> 8, e = i & 255;
        pp[l][e] = tree_emb[((size_t)u*nn + nodes[l])*EDIM + e];
    }
    __syncthreads();
    for (int i = t; i < 6*EDIM; i += 128){
        int l = i >> 8, e = i & 255;
        hh[l][e] = tanhf(lp[e] + pp[l][e]);
    }
    __syncthreads();

    float acc[6] = {0.f,0.f,0.f,0.f,0.f,0.f};
    for (int e = 0; e < EDIM; e++){
        float w = w1[e*128 + t];
        #pragma unroll
        for (int l = 0; l < 6; l++) acc[l] += hh[l][e] * w;
    }
    const float b1j = b1[t], w2j = w2[t];
    float part[6];
    #pragma unroll
    for (int l = 0; l < 6; l++) part[l] = fmaxf(acc[l] + b1j, 0.f) * w2j;
    #pragma unroll
    for (int o = 16; o > 0; o >>= 1){
        #pragma unroll
        for (int l = 0; l < 6; l++) part[l] += __shfl_xor_sync(0xFFFFFFFFu, part[l], o);
    }
    if (lane == 0){
        #pragma unroll
        for (int l = 0; l < 6; l++) red[l][wid] = part[l];
    }
    __syncthreads();

    const float b2v = b2[0];
    float a[6], amax = -3.0e38f;
    #pragma unroll
    for (int l = 0; l < 6; l++){
        float v = red[l][0] + red[l][1] + red[l][2] + red[l][3] + b2v;
        if (!msk[l]) v = -1e9f;
        a[l] = v; amax = fmaxf(amax, v);
    }
    float s = 0.f, aw[6];
    #pragma unroll
    for (int l = 0; l < 6; l++){ aw[l] = expf(a[l] - amax); s += aw[l]; }
    const float inv = 1.f / s;
    for (int e = t; e < EDIM; e += 128){
        float o = 0.f;
        #pragma unroll
        for (int l = 0; l < 6; l++) o += aw[l] * pp[l][e];
        g_prefh[(size_t)b*EDIM + e] = __float2half_rn(o * inv);
    }
}

// ---------------- kernel 2: GEMM (mma.sync fp16, fp32 acc) ----------------
// Tile 128x128, K-chunk 32 halves, 3-stage cp.async, 2 CTAs/SM.
// SMEM rows padded to 40 halves -> conflict-free 32-bit fragment LDS.
#define ROWH 40
#define AHALF_BYTES (128*ROWH*2)             // 10240
#define STAGE_BYTES (2*AHALF_BYTES)          // 20480
#define NSTAGE 3
#define GSMEM_BYTES (NSTAGE*STAGE_BYTES)     // 61440

__global__ void __launch_bounds__(256, 2)
gemm_kernel(float* __restrict__ out, int Brows, int Ncols)
{
    extern __shared__ char smem[];
    const uint32_t sb = smem_u32(smem);
    const int t = threadIdx.x;
    const int wid = t >> 5, lane = t & 31;
    const int g = lane >> 2, tq = lane & 3;
    const int wm = wid & 1, wn = wid >> 1;        // 2 x 4 warp grid
    const int m_base = blockIdx.x * 128;
    const int n_base = blockIdx.y * 128;

    const int lrow = t >> 2;          // 0..63 (64 rows/pass, 2 passes)
    const int lseg = t & 3;           // 16B segment (8 halves) in 64B row-chunk

    float acc[4][4][4];
    #pragma unroll
    for (int i = 0; i < 4; i++)
        #pragma unroll
        for (int j = 0; j < 4; j++)
            #pragma unroll
            for (int r = 0; r < 4; r++) acc[i][j][r] = 0.f;

    auto prefetch = [&](int kc){
        if (kc < 8){
            const uint32_t base = sb + (kc % NSTAGE)*STAGE_BYTES;
            #pragma unroll
            for (int it = 0; it < 2; it++){
                int row = lrow + it*64;
                cp_async16(base + row*(ROWH*2) + lseg*16,
                           &g_prefh[(size_t)(m_base+row)*EDIM + kc*32 + lseg*8], 16);
            }
            #pragma unroll
            for (int it = 0; it < 2; it++){
                int row = lrow + it*64;
                int gn = n_base + row;
                const __half* src = &g_bh[(size_t)(gn < Ncols ? gn : 0)*EDIM + kc*32 + lseg*8];
                cp_async16(base + AHALF_BYTES + row*(ROWH*2) + lseg*16, src, gn < Ncols ? 16 : 0);
            }
        }
        CP_COMMIT();
    };

    prefetch(0);
    prefetch(1);

    for (int kc = 0; kc < 8; kc++){
        CP_WAIT(NSTAGE - 2);
        __syncthreads();
        prefetch(kc + 2);

        const __half* As_ = (const __half*)(smem + (kc % NSTAGE)*STAGE_BYTES);
        const __half* Bs_ = (const __half*)(smem + (kc % NSTAGE)*STAGE_BYTES + AHALF_BYTES);

        #pragma unroll
        for (int ks = 0; ks < 2; ks++){
            const int k = ks * 16;
            uint32_t a[4][4], bf[4][2];
            #pragma unroll
            for (int i = 0; i < 4; i++){
                int r0 = wm*64 + i*16 + g;
                a[i][0] = *reinterpret_cast<const uint32_t*>(&As_[r0*ROWH + k + 2*tq]);
                a[i][1] = *reinterpret_cast<const uint32_t*>(&As_[(r0+8)*ROWH + k + 2*tq]);
                a[i][2] = *reinterpret_cast<const uint32_t*>(&As_[r0*ROWH + k + 2*tq + 8]);
                a[i][3] = *reinterpret_cast<const uint32_t*>(&As_[(r0+8)*ROWH + k + 2*tq + 8]);
            }
            #pragma unroll
            for (int j = 0; j < 4; j++){
                int n0 = wn*32 + j*8 + g;
                bf[j][0] = *reinterpret_cast<const uint32_t*>(&Bs_[n0*ROWH + k + 2*tq]);
                bf[j][1] = *reinterpret_cast<const uint32_t*>(&Bs_[n0*ROWH + k + 2*tq + 8]);
            }
            #pragma unroll
            for (int i = 0; i < 4; i++)
                #pragma unroll
                for (int j = 0; j < 4; j++)
                    mma_f16(acc[i][j], a[i], bf[j][0], bf[j][1]);
        }
    }

    // epilogue: streaming float2 stores
    #pragma unroll
    for (int i = 0; i < 4; i++){
        const int row0 = m_base + wm*64 + i*16 + g;
        #pragma unroll
        for (int j = 0; j < 4; j++){
            const int col = n_base + wn*32 + j*8 + 2*tq;
            if (col < Ncols && row0 < Brows){
                float2 v0 = make_float2(acc[i][j][0], acc[i][j][1]);
                float2 v1 = make_float2(acc[i][j][2], acc[i][j][3]);
                __stcs(reinterpret_cast<float2*>(&out[(size_t)row0*Ncols + col]), v0);
                __stcs(reinterpret_cast<float2*>(&out[(size_t)(row0+8)*Ncols + col]), v1);
            }
        }
    }
}

// ---------------- launch ----------------
extern "C" void kernel_launch(void* const* d_in, const int* in_sizes, int n_in,
                              void* d_out, int out_size)
{
    const int* user       = (const int*)d_in[0];
    const int* last_poi   = (const int*)d_in[1];
    const int* path_nodes = (const int*)d_in[2];
    const void* mask      = d_in[3];
    const int* nn_ptr = nullptr;
    int k = 4;
    if (n_in >= 11){ nn_ptr = (const int*)d_in[4]; k = 5; }
    const float* poi_emb  = (const float*)d_in[k+0];
    const float* tree_emb = (const float*)d_in[k+1];
    const float* w1 = (const float*)d_in[k+2];
    const float* b1 = (const float*)d_in[k+3];
    const float* w2 = (const float*)d_in[k+4];
    const float* b2 = (const float*)d_in[k+5];
    float* out = (float*)d_out;

    const int B  = in_sizes[0];
    const int NB = in_sizes[k+0];        // poi_emb elements
    const int NP = NB / EDIM;
    const int gridM = (B + 127) / 128;
    const int gridN = (NP + 127) / 128;

    detect_mask_kernel<<<1, 256>>>((const unsigned int*)mask);
    convert_b_kernel<<<(NB/8 + 255)/256, 256>>>(poi_emb, NB);
    attn_kernel<<<B, 128>>>(user, last_poi, path_nodes, mask, nn_ptr,
                            poi_emb, tree_emb, w1, b1, w2, b2);
    cudaFuncSetAttribute(gemm_kernel,
                         cudaFuncAttributeMaxDynamicSharedMemorySize, GSMEM_BYTES);
    dim3 grid(gridM, gridN);
    gemm_kernel<<<grid, 256, GSMEM_BYTES>>>(out, B, NP);
}

// round 8
// speedup vs baseline: 1.6975x; 1.1543x over previous
#include <cuda_runtime.h>
#include <cuda_fp16.h>
#include <cstdint>

#define EDIM 256

__device__ __half g_prefh[2048 * EDIM];
__device__ __half g_bh[100000 * EDIM];
__device__ int    g_mask_mode;

static __device__ __forceinline__ uint32_t smem_u32(const void* p){
    uint32_t a;
    asm("{ .reg .u64 t; cvta.to.shared.u64 t, %1; cvt.u32.u64 %0, t; }" : "=r"(a) : "l"(p));
    return a;
}
static __device__ __forceinline__ void cp_async16(uint32_t dst, const void* src, int src_bytes){
    asm volatile("cp.async.ca.shared.global [%0], [%1], 16, %2;"
                 :: "r"(dst), "l"(src), "r"(src_bytes) : "memory");
}
#define CP_COMMIT() asm volatile("cp.async.commit_group;" ::: "memory")
#define CP_WAIT(n)  asm volatile("cp.async.wait_group %0;" :: "n"(n) : "memory")

static __device__ __forceinline__ void mma_f16(float* d, const uint32_t* a,
                                               uint32_t b0, uint32_t b1){
    asm volatile(
        "mma.sync.aligned.m16n8k16.row.col.f32.f16.f16.f32 "
        "{%0,%1,%2,%3}, {%4,%5,%6,%7}, {%8,%9}, {%0,%1,%2,%3};"
        : "+f"(d[0]), "+f"(d[1]), "+f"(d[2]), "+f"(d[3])
        : "r"(a[0]), "r"(a[1]), "r"(a[2]), "r"(a[3]), "r"(b0), "r"(b1));
}
static __device__ __forceinline__ void ldsm_x4(uint32_t* r, uint32_t addr){
    asm volatile("ldmatrix.sync.aligned.m8n8.x4.shared.b16 {%0,%1,%2,%3}, [%4];"
                 : "=r"(r[0]), "=r"(r[1]), "=r"(r[2]), "=r"(r[3]) : "r"(addr));
}

// ---------------- kernel 0: detect path_mask dtype ----------------
__global__ void detect_mask_kernel(const unsigned int* __restrict__ m){
    __shared__ int sf, sg;
    if (threadIdx.x == 0){ sf = 0; sg = 0; }
    __syncthreads();
    int lf = 0, lg = 0;
    for (int i = threadIdx.x; i < 3072; i += blockDim.x){
        unsigned v = m[i];
        if (v == 0x3F800000u) lf = 1;
        else if (v > 1u) lg = 1;
    }
    if (lf) atomicOr(&sf, 1);
    if (lg) atomicOr(&sg, 1);
    __syncthreads();
    if (threadIdx.x == 0) g_mask_mode = sf ? 2 : (sg ? 1 : 0);
}

// ---------------- kernel 0b: poi_emb fp32 -> fp16 ----------------
__global__ void __launch_bounds__(256)
convert_b_kernel(const float* __restrict__ B, int n){
    int i = (blockIdx.x * 256 + threadIdx.x) * 8;
    if (i + 8 <= n){
        float4 v0 = *reinterpret_cast<const float4*>(B + i);
        float4 v1 = *reinterpret_cast<const float4*>(B + i + 4);
        __half2 h0 = __floats2half2_rn(v0.x, v0.y);
        __half2 h1 = __floats2half2_rn(v0.z, v0.w);
        __half2 h2 = __floats2half2_rn(v1.x, v1.y);
        __half2 h3 = __floats2half2_rn(v1.z, v1.w);
        uint4 o;
        o.x = *reinterpret_cast<uint32_t*>(&h0);
        o.y = *reinterpret_cast<uint32_t*>(&h1);
        o.z = *reinterpret_cast<uint32_t*>(&h2);
        o.w = *reinterpret_cast<uint32_t*>(&h3);
        *reinterpret_cast<uint4*>(&g_bh[i]) = o;
    } else {
        for (int j = i; j < n; j++) g_bh[j] = __float2half_rn(B[j]);
    }
}

// ---------------- kernel 1: attention -> g_prefh ----------------
__global__ void __launch_bounds__(128)
attn_kernel(const int* __restrict__ user, const int* __restrict__ last_poi,
            const int* __restrict__ path_nodes, const void* __restrict__ mask,
            const int* __restrict__ nn_ptr,
            const float* __restrict__ poi_emb, const float* __restrict__ tree_emb,
            const float* __restrict__ w1, const float* __restrict__ b1,
            const float* __restrict__ w2, const float* __restrict__ b2)
{
    const int b = blockIdx.x, t = threadIdx.x;
    const int wid = t >> 5, lane = t & 31;
    __shared__ float lp[EDIM];
    __shared__ float pp[6][EDIM];
    __shared__ float hh[6][EDIM];
    __shared__ float red[6][4];

    const int mode = g_mask_mode;
    const int nn = nn_ptr ? nn_ptr[0] : 63;
    const int u = user[b];
    const int poi = last_poi[b];

    int nodes[6]; bool msk[6];
    #pragma unroll
    for (int l = 0; l < 6; l++) nodes[l] = path_nodes[b*6 + l];
    if (mode == 2){
        const float* mm = (const float*)mask;
        #pragma unroll
        for (int l = 0; l < 6; l++) msk[l] = (mm[b*6+l] != 0.f);
    } else if (mode == 1){
        const unsigned char* mm = (const unsigned char*)mask;
        #pragma unroll
        for (int l = 0; l < 6; l++) msk[l] = (mm[b*6+l] != 0);
    } else {
        const int* mm = (const int*)mask;
        #pragma unroll
        for (int l = 0; l < 6; l++) msk[l] = (mm[b*6+l] != 0);
    }

    for (int e = t; e < EDIM; e += 128) lp[e] = poi_emb[(size_t)poi*EDIM + e];
    for (int i = t; i < 6*EDIM; i += 128){
        int l = i >> 8, e = i & 255;
        pp[l][e] = tree_emb[((size_t)u*nn + nodes[l])*EDIM + e];
    }
    __syncthreads();
    for (int i = t; i < 6*EDIM; i += 128){
        int l = i >> 8, e = i & 255;
        hh[l][e] = tanhf(lp[e] + pp[l][e]);
    }
    __syncthreads();

    float acc[6] = {0.f,0.f,0.f,0.f,0.f,0.f};
    for (int e = 0; e < EDIM; e++){
        float w = w1[e*128 + t];
        #pragma unroll
        for (int l = 0; l < 6; l++) acc[l] += hh[l][e] * w;
    }
    const float b1j = b1[t], w2j = w2[t];
    float part[6];
    #pragma unroll
    for (int l = 0; l < 6; l++) part[l] = fmaxf(acc[l] + b1j, 0.f) * w2j;
    #pragma unroll
    for (int o = 16; o > 0; o >>= 1){
        #pragma unroll
        for (int l = 0; l < 6; l++) part[l] += __shfl_xor_sync(0xFFFFFFFFu, part[l], o);
    }
    if (lane == 0){
        #pragma unroll
        for (int l = 0; l < 6; l++) red[l][wid] = part[l];
    }
    __syncthreads();

    const float b2v = b2[0];
    float a[6], amax = -3.0e38f;
    #pragma unroll
    for (int l = 0; l < 6; l++){
        float v = red[l][0] + red[l][1] + red[l][2] + red[l][3] + b2v;
        if (!msk[l]) v = -1e9f;
        a[l] = v; amax = fmaxf(amax, v);
    }
    float s = 0.f, aw[6];
    #pragma unroll
    for (int l = 0; l < 6; l++){ aw[l] = expf(a[l] - amax); s += aw[l]; }
    const float inv = 1.f / s;
    for (int e = t; e < EDIM; e += 128){
        float o = 0.f;
        #pragma unroll
        for (int l = 0; l < 6; l++) o += aw[l] * pp[l][e];
        g_prefh[(size_t)b*EDIM + e] = __float2half_rn(o * inv);
    }
}

// ---------------- kernel 2: GEMM (mma.sync fp16, ldmatrix fragments) ----------------
// Tile 128x128, K-chunk 32 halves, 3-stage cp.async, 2 CTAs/SM.
// SMEM rows padded to 40 halves -> conflict-free for both cp.async STS and LDSM.
#define ROWH 40
#define AHALF_BYTES (128*ROWH*2)             // 10240
#define STAGE_BYTES (2*AHALF_BYTES)          // 20480
#define NSTAGE 3
#define GSMEM_BYTES (NSTAGE*STAGE_BYTES)     // 61440

__global__ void __launch_bounds__(256, 2)
gemm_kernel(float* __restrict__ out, int Brows, int Ncols)
{
    extern __shared__ char smem[];
    const uint32_t sb = smem_u32(smem);
    const int t = threadIdx.x;
    const int wid = t >> 5, lane = t & 31;
    const int g = lane >> 2, tq = lane & 3;
    const int wm = wid & 1, wn = wid >> 1;        // 2 x 4 warp grid
    const int m_base = blockIdx.x * 128;
    const int n_base = blockIdx.y * 128;

    const int lrow = t >> 2;          // 0..63 (64 rows/pass, 2 passes)
    const int lseg = t & 3;           // 16B segment (8 halves) in 64B row-chunk

    // ldmatrix lane->pointer precompute
    const int lr  = lane & 7;         // row within 8x8 matrix
    const int sel = lane >> 3;        // which of the 4 matrices
    // A tile i (m16k16): matrices (rows+0,k+0),(rows+8,k+0),(rows+0,k+8),(rows+8,k+8)
    uint32_t a_off[4];
    #pragma unroll
    for (int i = 0; i < 4; i++){
        int row = wm*64 + i*16 + (sel & 1)*8 + lr;
        a_off[i] = (uint32_t)(row*(ROWH*2) + ((sel >> 1)*8)*2);
    }
    // B pair jp (two n8k16 tiles): matrices (j,k+0),(j,k+8),(j+1,k+0),(j+1,k+8)
    uint32_t b_off[2];
    #pragma unroll
    for (int jp = 0; jp < 2; jp++){
        int n = wn*32 + jp*16 + (sel >> 1)*8 + lr;
        b_off[jp] = (uint32_t)(AHALF_BYTES + n*(ROWH*2) + ((sel & 1)*8)*2);
    }

    float acc[4][4][4];
    #pragma unroll
    for (int i = 0; i < 4; i++)
        #pragma unroll
        for (int j = 0; j < 4; j++)
            #pragma unroll
            for (int r = 0; r < 4; r++) acc[i][j][r] = 0.f;

    auto prefetch = [&](int kc){
        if (kc < 8){
            const uint32_t base = sb + (kc % NSTAGE)*STAGE_BYTES;
            #pragma unroll
            for (int it = 0; it < 2; it++){
                int row = lrow + it*64;
                cp_async16(base + row*(ROWH*2) + lseg*16,
                           &g_prefh[(size_t)(m_base+row)*EDIM + kc*32 + lseg*8], 16);
            }
            #pragma unroll
            for (int it = 0; it < 2; it++){
                int row = lrow + it*64;
                int gn = n_base + row;
                const __half* src = &g_bh[(size_t)(gn < Ncols ? gn : 0)*EDIM + kc*32 + lseg*8];
                cp_async16(base + AHALF_BYTES + row*(ROWH*2) + lseg*16, src, gn < Ncols ? 16 : 0);
            }
        }
        CP_COMMIT();
    };

    prefetch(0);
    prefetch(1);

    for (int kc = 0; kc < 8; kc++){
        CP_WAIT(NSTAGE - 2);
        __syncthreads();
        prefetch(kc + 2);

        const uint32_t stage = sb + (kc % NSTAGE)*STAGE_BYTES;

        #pragma unroll
        for (int ks = 0; ks < 2; ks++){
            const uint32_t kb = (uint32_t)(ks * 16 * 2);   // byte offset of k within row
            uint32_t a[4][4], bf[4][2];
            #pragma unroll
            for (int i = 0; i < 4; i++)
                ldsm_x4(a[i], stage + a_off[i] + kb);
            #pragma unroll
            for (int jp = 0; jp < 2; jp++){
                uint32_t r[4];
                ldsm_x4(r, stage + b_off[jp] + kb);
                bf[2*jp][0]   = r[0];  bf[2*jp][1]   = r[1];
                bf[2*jp+1][0] = r[2];  bf[2*jp+1][1] = r[3];
            }
            #pragma unroll
            for (int i = 0; i < 4; i++)
                #pragma unroll
                for (int j = 0; j < 4; j++)
                    mma_f16(acc[i][j], a[i], bf[j][0], bf[j][1]);
        }
    }

    // epilogue: streaming float2 stores
    #pragma unroll
    for (int i = 0; i < 4; i++){
        const int row0 = m_base + wm*64 + i*16 + g;
        #pragma unroll
        for (int j = 0; j < 4; j++){
            const int col = n_base + wn*32 + j*8 + 2*tq;
            if (col < Ncols && row0 < Brows){
                float2 v0 = make_float2(acc[i][j][0], acc[i][j][1]);
                float2 v1 = make_float2(acc[i][j][2], acc[i][j][3]);
                __stcs(reinterpret_cast<float2*>(&out[(size_t)row0*Ncols + col]), v0);
                __stcs(reinterpret_cast<float2*>(&out[(size_t)(row0+8)*Ncols + col]), v1);
            }
        }
    }
}

// ---------------- launch ----------------
extern "C" void kernel_launch(void* const* d_in, const int* in_sizes, int n_in,
                              void* d_out, int out_size)
{
    const int* user       = (const int*)d_in[0];
    const int* last_poi   = (const int*)d_in[1];
    const int* path_nodes = (const int*)d_in[2];
    const void* mask      = d_in[3];
    const int* nn_ptr = nullptr;
    int k = 4;
    if (n_in >= 11){ nn_ptr = (const int*)d_in[4]; k = 5; }
    const float* poi_emb  = (const float*)d_in[k+0];
    const float* tree_emb = (const float*)d_in[k+1];
    const float* w1 = (const float*)d_in[k+2];
    const float* b1 = (const float*)d_in[k+3];
    const float* w2 = (const float*)d_in[k+4];
    const float* b2 = (const float*)d_in[k+5];
    float* out = (float*)d_out;

    const int B  = in_sizes[0];
    const int NB = in_sizes[k+0];        // poi_emb elements
    const int NP = NB / EDIM;
    const int gridM = (B + 127) / 128;
    const int gridN = (NP + 127) / 128;

    detect_mask_kernel<<<1, 256>>>((const unsigned int*)mask);
    convert_b_kernel<<<(NB/8 + 255)/256, 256>>>(poi_emb, NB);
    attn_kernel<<<B, 128>>>(user, last_poi, path_nodes, mask, nn_ptr,
                            poi_emb, tree_emb, w1, b1, w2, b2);
    cudaFuncSetAttribute(gemm_kernel,
                         cudaFuncAttributeMaxDynamicSharedMemorySize, GSMEM_BYTES);
    dim3 grid(gridM, gridN);
    gemm_kernel<<<grid, 256, GSMEM_BYTES>>>(out, B, NP);
}